// round 1
// baseline (speedup 1.0000x reference)
#include <cuda_runtime.h>

// ============================================================================
// SimpleMACELayer on GB300 — Round 1 (SIMT fp32 baseline, fused design)
//
// out[n,o'] = b[o'] + sum_{e: dst(e)=n} v[e,o']
// v[e,o']   = sum_{q,h} u[e,h,q] * M[q,h,o']
// u[e,h,q]  = sum_{i in s1} src[e,h,i] * A[e,q,i]
// A[e,q,i]  = sum_{j in s2} Y[e,j] * cg[i,j,k(q)]
// M[q,h,o'] = sum_o tp_w[p(q),h,o] * W_lin[o', o*16 + k(q)]   (precomputed)
//
// q enumerates (path p, k in s3(p)) pairs: 99 total. K-dim of the big GEMM
// is (q,h) = 6336. All hot data (node_features 5.1MB, M 1.6MB, cg 16KB,
// out 5.1MB) is L2-resident.
// ============================================================================

#define NPATH 23
#define Q_TOTAL 99
#define EPB 64          // edges per block
#define NTHREADS 256

// Paths in the reference's enumeration order (l1 outer, then l2, then l3 asc,
// with |l1-l2|<=l3<=min(l1+l2,3) and (l1+l2+l3) even):
__constant__ int cPL2[NPATH] = {0,1,2,3, 0,1,1,2,2,3, 0,1,1,2,2,3,3, 0,1,2,2,3,3};
__constant__ int cPL3[NPATH] = {0,1,2,3, 1,0,2,1,3,2, 2,1,3,0,2,1,3, 3,2,1,3,0,2};
// Path index ranges per l1 group (paths are contiguous by l1):
__constant__ int cPSTART[5] = {0,4,10,17,23};

// Fused weight tensor M[q][h][o'] : 99*64*64 floats = 1.6 MB scratch.
__device__ float g_M[Q_TOTAL * 64 * 64];

// ----------------------------------------------------------------------------
// Kernel 1: build M[q,h,o'] = sum_o tp_w[p(q),h,o] * W_lin[o', o*16 + k(q)]
// ----------------------------------------------------------------------------
__global__ void build_M_kernel(const float* __restrict__ tw,
                               const float* __restrict__ wlin) {
    int q = blockIdx.x;
    // map q -> (p, global k)
    int p = 0, k0 = 0;
    for (; p < NPATH; ++p) {
        int c = 2 * cPL3[p] + 1;
        if (q < k0 + c) break;
        k0 += c;
    }
    int l3 = cPL3[p];
    int kg = l3 * l3 + (q - k0);

    __shared__ float twS[4096];  // [h][o]
    __shared__ float wlS[4096];  // [o][o']  (o-major so the dot loop is conflict-free)

    for (int i = threadIdx.x; i < 4096; i += blockDim.x)
        twS[i] = tw[p * 4096 + i];
    for (int i = threadIdx.x; i < 4096; i += blockDim.x) {
        int o = i >> 6, op = i & 63;
        wlS[o * 64 + op] = wlin[op * 1024 + o * 16 + kg];
    }
    __syncthreads();

    for (int r = threadIdx.x; r < 4096; r += blockDim.x) {
        int h = r >> 6, op = r & 63;
        float acc = 0.0f;
#pragma unroll 8
        for (int o = 0; o < 64; ++o)
            acc += twS[h * 64 + o] * wlS[o * 64 + op];
        g_M[(q * 64 + h) * 64 + op] = acc;
    }
}

// ----------------------------------------------------------------------------
// Kernel 2: initialize out[n,o'] = b[o']
// ----------------------------------------------------------------------------
__global__ void init_out_kernel(float* __restrict__ out,
                                const float* __restrict__ b, int total) {
    int i = blockIdx.x * blockDim.x + threadIdx.x;
    if (i < total) out[i] = b[i & 63];
}

// ----------------------------------------------------------------------------
// Kernel 3: main edge kernel. One block = 64 edges.
// Per block: compute Y, gather src features (per-l1 column slices),
// stream over the 99 q-steps: A -> Uq -> accumulate V += Uq^T @ M_q.
// Finish with 64 atomicAdds per edge into out[dst].
//
// Dynamic smem layout (bytes):
//   sSrc 7*64*64*4 = 114688   [ic][h][e]
//   sUq  64*64*4   =  16384   [h][e]
//   sMs  64*64*4   =  16384   [h][o']
//   sY   16*64*4   =   4096   [j][e]
//   sA   7*64*4    =   1792   [ic][e]
//   idx  2*64*4    =    512
//   total          = 153856
// ----------------------------------------------------------------------------
__global__ __launch_bounds__(NTHREADS, 1)
void edge_kernel(const float* __restrict__ nf,
                 const float* __restrict__ ev,
                 const int*   __restrict__ ei,
                 const float* __restrict__ cg,
                 float*       __restrict__ out,
                 int E) {
    extern __shared__ float sm[];
    float* sSrc = sm;                    // 7*4096
    float* sUq  = sm + 7 * 4096;        // 4096
    float* sMs  = sUq + 4096;           // 4096
    float* sY   = sMs + 4096;           // 1024
    float* sA   = sY + 1024;            // 448
    int*   sSrcIdx = (int*)(sA + 448);  // 64
    int*   sDstIdx = sSrcIdx + 64;      // 64

    const int tid = threadIdx.x;
    const int e0  = blockIdx.x * EPB;

    // --- Phase 0: per-edge Y + indices ---
    if (tid < EPB) {
        int e = e0 + tid;
        if (e < E) {
            float x = ev[e * 3 + 0];
            float y = ev[e * 3 + 1];
            float z = ev[e * 3 + 2];
            float x2 = x * x, y2 = y * y, z2 = z * z;
            float Y[16];
            Y[0]  = 0.28209479177387814f;
            Y[1]  = 0.4886025119029199f * y;
            Y[2]  = 0.4886025119029199f * z;
            Y[3]  = 0.4886025119029199f * x;
            Y[4]  = 1.0925484305920792f * x * y;
            Y[5]  = 1.0925484305920792f * y * z;
            Y[6]  = 0.31539156525252005f * (3.0f * z2 - 1.0f);
            Y[7]  = 1.0925484305920792f * x * z;
            Y[8]  = 0.5462742152960396f * (x2 - y2);
            Y[9]  = 0.5900435899266435f * y * (3.0f * x2 - y2);
            Y[10] = 2.890611442640554f * x * y * z;
            Y[11] = 0.4570457994644658f * y * (5.0f * z2 - 1.0f);
            Y[12] = 0.3731763325901154f * z * (5.0f * z2 - 3.0f);
            Y[13] = 0.4570457994644658f * x * (5.0f * z2 - 1.0f);
            Y[14] = 1.445305721320277f * z * (x2 - y2);
            Y[15] = 0.5900435899266435f * x * (x2 - 3.0f * y2);
#pragma unroll
            for (int j = 0; j < 16; ++j) sY[j * 64 + tid] = Y[j];
            sSrcIdx[tid] = ei[e];       // src row of edge_index
            sDstIdx[tid] = ei[E + e];   // dst row
        } else {
#pragma unroll
            for (int j = 0; j < 16; ++j) sY[j * 64 + tid] = 0.0f;
            sSrcIdx[tid] = 0;
            sDstIdx[tid] = -1;
        }
    }

    // V accumulators: 4 edges x 4 outputs per thread. 16x16 thread grid.
    float V[16];
#pragma unroll
    for (int i = 0; i < 16; ++i) V[i] = 0.0f;
    const int tx = tid & 15;   // o' group
    const int ty = tid >> 4;   // e group

    __syncthreads();

    int q = 0;
    for (int g = 0; g < 4; ++g) {
        const int nc = 2 * g + 1;
        const int i0 = g * g;

        // --- load src feature slice for this l1 group: sSrc[ic][h][e] ---
        for (int idx = tid; idx < nc * 4096; idx += NTHREADS) {
            int e = idx & 63;
            int rest = idx >> 6;
            int h = rest & 63;
            int ic = rest >> 6;
            sSrc[ic * 4096 + h * 64 + e] =
                __ldg(&nf[(long)sSrcIdx[e] * 1024 + h * 16 + i0 + ic]);
        }
        __syncthreads();

        for (int p = cPSTART[g]; p < cPSTART[g + 1]; ++p) {
            const int l2 = cPL2[p];
            const int l3 = cPL3[p];
            const int j0 = l2 * l2, nj = 2 * l2 + 1;
            const int k00 = l3 * l3, nk = 2 * l3 + 1;

            for (int kl = 0; kl < nk; ++kl, ++q) {
                const int kg = k00 + kl;

                // load M_q tile [h][o'] (16KB, L2-resident, coalesced float4)
                {
                    const float4* gm = (const float4*)(g_M + q * 4096);
                    float4* s4 = (float4*)sMs;
                    for (int i = tid; i < 1024; i += NTHREADS) s4[i] = gm[i];
                }
                // compute A[ic][e] = sum_j Y[j][e] * cg[i0+ic, j0+j, kg]
                for (int idx = tid; idx < nc * 64; idx += NTHREADS) {
                    int ic = idx >> 6, e = idx & 63;
                    float acc = 0.0f;
                    for (int jc = 0; jc < nj; ++jc)
                        acc += sY[(j0 + jc) * 64 + e] *
                               __ldg(&cg[(i0 + ic) * 256 + (j0 + jc) * 16 + kg]);
                    sA[ic * 64 + e] = acc;
                }
                __syncthreads();

                // compute Uq[h][e] = sum_ic sSrc[ic][h][e] * A[ic][e]
#pragma unroll
                for (int r = 0; r < 16; ++r) {
                    int idx = r * NTHREADS + tid;
                    int h = idx >> 6, e = idx & 63;
                    float acc = 0.0f;
                    for (int ic = 0; ic < nc; ++ic)
                        acc += sSrc[ic * 4096 + h * 64 + e] * sA[ic * 64 + e];
                    sUq[h * 64 + e] = acc;
                }
                __syncthreads();

                // GEMM: V[e 4][o' 4] += sum_h Uq[h][e] * Ms[h][o']
#pragma unroll 4
                for (int kk = 0; kk < 64; ++kk) {
                    const float4 u = *reinterpret_cast<const float4*>(
                        sUq + kk * 64 + (ty << 2));
                    const float4 m = *reinterpret_cast<const float4*>(
                        sMs + kk * 64 + (tx << 2));
                    V[0]  += u.x * m.x; V[1]  += u.x * m.y;
                    V[2]  += u.x * m.z; V[3]  += u.x * m.w;
                    V[4]  += u.y * m.x; V[5]  += u.y * m.y;
                    V[6]  += u.y * m.z; V[7]  += u.y * m.w;
                    V[8]  += u.z * m.x; V[9]  += u.z * m.y;
                    V[10] += u.z * m.z; V[11] += u.z * m.w;
                    V[12] += u.w * m.x; V[13] += u.w * m.y;
                    V[14] += u.w * m.z; V[15] += u.w * m.w;
                }
                __syncthreads();
            }
        }
        // last inner __syncthreads() protects sSrc reload
    }

    // --- scatter: atomicAdd into out[dst] ---
#pragma unroll
    for (int a = 0; a < 4; ++a) {
        int e = (ty << 2) + a;
        int d = sDstIdx[e];
        if (d >= 0) {
            float* dst = out + d * 64 + (tx << 2);
            atomicAdd(dst + 0, V[a * 4 + 0]);
            atomicAdd(dst + 1, V[a * 4 + 1]);
            atomicAdd(dst + 2, V[a * 4 + 2]);
            atomicAdd(dst + 3, V[a * 4 + 3]);
        }
    }
}

// ----------------------------------------------------------------------------
extern "C" void kernel_launch(void* const* d_in, const int* in_sizes, int n_in,
                              void* d_out, int out_size) {
    const float* nf   = (const float*)d_in[0];  // node_features
    const float* ev   = (const float*)d_in[1];  // edge_vectors
    const int*   ei   = (const int*)  d_in[2];  // edge_index
    const float* cg   = (const float*)d_in[3];  // gaunt coeffs
    const float* tw   = (const float*)d_in[4];  // tp_weights
    const float* wlin = (const float*)d_in[5];  // W_lin
    const float* bl   = (const float*)d_in[6];  // b_lin
    float* out = (float*)d_out;

    const int E = in_sizes[1] / 3;
    const int N = in_sizes[0] / (64 * 16);

    const int SMEM = 153856;
    cudaFuncSetAttribute(edge_kernel,
                         cudaFuncAttributeMaxDynamicSharedMemorySize, SMEM);

    build_M_kernel<<<Q_TOTAL, 256>>>(tw, wlin);
    init_out_kernel<<<(N * 64 + 255) / 256, 256>>>(out, bl, N * 64);
    edge_kernel<<<(E + EPB - 1) / EPB, NTHREADS, SMEM>>>(nf, ev, ei, cg, out, E);
}

// round 2
// speedup vs baseline: 1.0008x; 1.0008x over previous
#include <cuda_runtime.h>

// ============================================================================
// SimpleMACELayer on GB300 — Round 1 (SIMT fp32 baseline, fused design)
//
// out[n,o'] = b[o'] + sum_{e: dst(e)=n} v[e,o']
// v[e,o']   = sum_{q,h} u[e,h,q] * M[q,h,o']
// u[e,h,q]  = sum_{i in s1} src[e,h,i] * A[e,q,i]
// A[e,q,i]  = sum_{j in s2} Y[e,j] * cg[i,j,k(q)]
// M[q,h,o'] = sum_o tp_w[p(q),h,o] * W_lin[o', o*16 + k(q)]   (precomputed)
//
// q enumerates (path p, k in s3(p)) pairs: 99 total. K-dim of the big GEMM
// is (q,h) = 6336. All hot data (node_features 5.1MB, M 1.6MB, cg 16KB,
// out 5.1MB) is L2-resident.
// ============================================================================

#define NPATH 23
#define Q_TOTAL 99
#define EPB 64          // edges per block
#define NTHREADS 256

// Paths in the reference's enumeration order (l1 outer, then l2, then l3 asc,
// with |l1-l2|<=l3<=min(l1+l2,3) and (l1+l2+l3) even):
__constant__ int cPL2[NPATH] = {0,1,2,3, 0,1,1,2,2,3, 0,1,1,2,2,3,3, 0,1,2,2,3,3};
__constant__ int cPL3[NPATH] = {0,1,2,3, 1,0,2,1,3,2, 2,1,3,0,2,1,3, 3,2,1,3,0,2};
// Path index ranges per l1 group (paths are contiguous by l1):
__constant__ int cPSTART[5] = {0,4,10,17,23};

// Fused weight tensor M[q][h][o'] : 99*64*64 floats = 1.6 MB scratch.
__device__ float g_M[Q_TOTAL * 64 * 64];

// ----------------------------------------------------------------------------
// Kernel 1: build M[q,h,o'] = sum_o tp_w[p(q),h,o] * W_lin[o', o*16 + k(q)]
// ----------------------------------------------------------------------------
__global__ void build_M_kernel(const float* __restrict__ tw,
                               const float* __restrict__ wlin) {
    int q = blockIdx.x;
    // map q -> (p, global k)
    int p = 0, k0 = 0;
    for (; p < NPATH; ++p) {
        int c = 2 * cPL3[p] + 1;
        if (q < k0 + c) break;
        k0 += c;
    }
    int l3 = cPL3[p];
    int kg = l3 * l3 + (q - k0);

    __shared__ float twS[4096];  // [h][o]
    __shared__ float wlS[4096];  // [o][o']  (o-major so the dot loop is conflict-free)

    for (int i = threadIdx.x; i < 4096; i += blockDim.x)
        twS[i] = tw[p * 4096 + i];
    for (int i = threadIdx.x; i < 4096; i += blockDim.x) {
        int o = i >> 6, op = i & 63;
        wlS[o * 64 + op] = wlin[op * 1024 + o * 16 + kg];
    }
    __syncthreads();

    for (int r = threadIdx.x; r < 4096; r += blockDim.x) {
        int h = r >> 6, op = r & 63;
        float acc = 0.0f;
#pragma unroll 8
        for (int o = 0; o < 64; ++o)
            acc += twS[h * 64 + o] * wlS[o * 64 + op];
        g_M[(q * 64 + h) * 64 + op] = acc;
    }
}

// ----------------------------------------------------------------------------
// Kernel 2: initialize out[n,o'] = b[o']
// ----------------------------------------------------------------------------
__global__ void init_out_kernel(float* __restrict__ out,
                                const float* __restrict__ b, int total) {
    int i = blockIdx.x * blockDim.x + threadIdx.x;
    if (i < total) out[i] = b[i & 63];
}

// ----------------------------------------------------------------------------
// Kernel 3: main edge kernel. One block = 64 edges.
// Per block: compute Y, gather src features (per-l1 column slices),
// stream over the 99 q-steps: A -> Uq -> accumulate V += Uq^T @ M_q.
// Finish with 64 atomicAdds per edge into out[dst].
//
// Dynamic smem layout (bytes):
//   sSrc 7*64*64*4 = 114688   [ic][h][e]
//   sUq  64*64*4   =  16384   [h][e]
//   sMs  64*64*4   =  16384   [h][o']
//   sY   16*64*4   =   4096   [j][e]
//   sA   7*64*4    =   1792   [ic][e]
//   idx  2*64*4    =    512
//   total          = 153856
// ----------------------------------------------------------------------------
__global__ __launch_bounds__(NTHREADS, 1)
void edge_kernel(const float* __restrict__ nf,
                 const float* __restrict__ ev,
                 const int*   __restrict__ ei,
                 const float* __restrict__ cg,
                 float*       __restrict__ out,
                 int E) {
    extern __shared__ float sm[];
    float* sSrc = sm;                    // 7*4096
    float* sUq  = sm + 7 * 4096;        // 4096
    float* sMs  = sUq + 4096;           // 4096
    float* sY   = sMs + 4096;           // 1024
    float* sA   = sY + 1024;            // 448
    int*   sSrcIdx = (int*)(sA + 448);  // 64
    int*   sDstIdx = sSrcIdx + 64;      // 64

    const int tid = threadIdx.x;
    const int e0  = blockIdx.x * EPB;

    // --- Phase 0: per-edge Y + indices ---
    if (tid < EPB) {
        int e = e0 + tid;
        if (e < E) {
            float x = ev[e * 3 + 0];
            float y = ev[e * 3 + 1];
            float z = ev[e * 3 + 2];
            float x2 = x * x, y2 = y * y, z2 = z * z;
            float Y[16];
            Y[0]  = 0.28209479177387814f;
            Y[1]  = 0.4886025119029199f * y;
            Y[2]  = 0.4886025119029199f * z;
            Y[3]  = 0.4886025119029199f * x;
            Y[4]  = 1.0925484305920792f * x * y;
            Y[5]  = 1.0925484305920792f * y * z;
            Y[6]  = 0.31539156525252005f * (3.0f * z2 - 1.0f);
            Y[7]  = 1.0925484305920792f * x * z;
            Y[8]  = 0.5462742152960396f * (x2 - y2);
            Y[9]  = 0.5900435899266435f * y * (3.0f * x2 - y2);
            Y[10] = 2.890611442640554f * x * y * z;
            Y[11] = 0.4570457994644658f * y * (5.0f * z2 - 1.0f);
            Y[12] = 0.3731763325901154f * z * (5.0f * z2 - 3.0f);
            Y[13] = 0.4570457994644658f * x * (5.0f * z2 - 1.0f);
            Y[14] = 1.445305721320277f * z * (x2 - y2);
            Y[15] = 0.5900435899266435f * x * (x2 - 3.0f * y2);
#pragma unroll
            for (int j = 0; j < 16; ++j) sY[j * 64 + tid] = Y[j];
            sSrcIdx[tid] = ei[e];       // src row of edge_index
            sDstIdx[tid] = ei[E + e];   // dst row
        } else {
#pragma unroll
            for (int j = 0; j < 16; ++j) sY[j * 64 + tid] = 0.0f;
            sSrcIdx[tid] = 0;
            sDstIdx[tid] = -1;
        }
    }

    // V accumulators: 4 edges x 4 outputs per thread. 16x16 thread grid.
    float V[16];
#pragma unroll
    for (int i = 0; i < 16; ++i) V[i] = 0.0f;
    const int tx = tid & 15;   // o' group
    const int ty = tid >> 4;   // e group

    __syncthreads();

    int q = 0;
    for (int g = 0; g < 4; ++g) {
        const int nc = 2 * g + 1;
        const int i0 = g * g;

        // --- load src feature slice for this l1 group: sSrc[ic][h][e] ---
        for (int idx = tid; idx < nc * 4096; idx += NTHREADS) {
            int e = idx & 63;
            int rest = idx >> 6;
            int h = rest & 63;
            int ic = rest >> 6;
            sSrc[ic * 4096 + h * 64 + e] =
                __ldg(&nf[(long)sSrcIdx[e] * 1024 + h * 16 + i0 + ic]);
        }
        __syncthreads();

        for (int p = cPSTART[g]; p < cPSTART[g + 1]; ++p) {
            const int l2 = cPL2[p];
            const int l3 = cPL3[p];
            const int j0 = l2 * l2, nj = 2 * l2 + 1;
            const int k00 = l3 * l3, nk = 2 * l3 + 1;

            for (int kl = 0; kl < nk; ++kl, ++q) {
                const int kg = k00 + kl;

                // load M_q tile [h][o'] (16KB, L2-resident, coalesced float4)
                {
                    const float4* gm = (const float4*)(g_M + q * 4096);
                    float4* s4 = (float4*)sMs;
                    for (int i = tid; i < 1024; i += NTHREADS) s4[i] = gm[i];
                }
                // compute A[ic][e] = sum_j Y[j][e] * cg[i0+ic, j0+j, kg]
                for (int idx = tid; idx < nc * 64; idx += NTHREADS) {
                    int ic = idx >> 6, e = idx & 63;
                    float acc = 0.0f;
                    for (int jc = 0; jc < nj; ++jc)
                        acc += sY[(j0 + jc) * 64 + e] *
                               __ldg(&cg[(i0 + ic) * 256 + (j0 + jc) * 16 + kg]);
                    sA[ic * 64 + e] = acc;
                }
                __syncthreads();

                // compute Uq[h][e] = sum_ic sSrc[ic][h][e] * A[ic][e]
#pragma unroll
                for (int r = 0; r < 16; ++r) {
                    int idx = r * NTHREADS + tid;
                    int h = idx >> 6, e = idx & 63;
                    float acc = 0.0f;
                    for (int ic = 0; ic < nc; ++ic)
                        acc += sSrc[ic * 4096 + h * 64 + e] * sA[ic * 64 + e];
                    sUq[h * 64 + e] = acc;
                }
                __syncthreads();

                // GEMM: V[e 4][o' 4] += sum_h Uq[h][e] * Ms[h][o']
#pragma unroll 4
                for (int kk = 0; kk < 64; ++kk) {
                    const float4 u = *reinterpret_cast<const float4*>(
                        sUq + kk * 64 + (ty << 2));
                    const float4 m = *reinterpret_cast<const float4*>(
                        sMs + kk * 64 + (tx << 2));
                    V[0]  += u.x * m.x; V[1]  += u.x * m.y;
                    V[2]  += u.x * m.z; V[3]  += u.x * m.w;
                    V[4]  += u.y * m.x; V[5]  += u.y * m.y;
                    V[6]  += u.y * m.z; V[7]  += u.y * m.w;
                    V[8]  += u.z * m.x; V[9]  += u.z * m.y;
                    V[10] += u.z * m.z; V[11] += u.z * m.w;
                    V[12] += u.w * m.x; V[13] += u.w * m.y;
                    V[14] += u.w * m.z; V[15] += u.w * m.w;
                }
                __syncthreads();
            }
        }
        // last inner __syncthreads() protects sSrc reload
    }

    // --- scatter: atomicAdd into out[dst] ---
#pragma unroll
    for (int a = 0; a < 4; ++a) {
        int e = (ty << 2) + a;
        int d = sDstIdx[e];
        if (d >= 0) {
            float* dst = out + d * 64 + (tx << 2);
            atomicAdd(dst + 0, V[a * 4 + 0]);
            atomicAdd(dst + 1, V[a * 4 + 1]);
            atomicAdd(dst + 2, V[a * 4 + 2]);
            atomicAdd(dst + 3, V[a * 4 + 3]);
        }
    }
}

// ----------------------------------------------------------------------------
extern "C" void kernel_launch(void* const* d_in, const int* in_sizes, int n_in,
                              void* d_out, int out_size) {
    const float* nf   = (const float*)d_in[0];  // node_features
    const float* ev   = (const float*)d_in[1];  // edge_vectors
    const int*   ei   = (const int*)  d_in[2];  // edge_index
    const float* cg   = (const float*)d_in[3];  // gaunt coeffs
    const float* tw   = (const float*)d_in[4];  // tp_weights
    const float* wlin = (const float*)d_in[5];  // W_lin
    const float* bl   = (const float*)d_in[6];  // b_lin
    float* out = (float*)d_out;

    const int E = in_sizes[1] / 3;
    const int N = in_sizes[0] / (64 * 16);

    const int SMEM = 153856;
    cudaFuncSetAttribute(edge_kernel,
                         cudaFuncAttributeMaxDynamicSharedMemorySize, SMEM);

    build_M_kernel<<<Q_TOTAL, 256>>>(tw, wlin);
    init_out_kernel<<<(N * 64 + 255) / 256, 256>>>(out, bl, N * 64);
    edge_kernel<<<(E + EPB - 1) / EPB, NTHREADS, SMEM>>>(nf, ev, ei, cg, out, E);
}